// round 3
// baseline (speedup 1.0000x reference)
#include <cuda_runtime.h>

// VQ-VAE nearest-codebook quantization, fused, with EXACT emulation of the
// reference's fp32 scoring so the argmin matches bitwise:
//   dot[m,k] = sequential ascending fp32 FMA chain over d (cublas sgemm order)
//   t2       = RN(x2[m] - 2*dot)        (2*dot exact; single rounding == FFMA)
//   s        = RN(t2 + e2[k])
//   idx[m]   = argmin_k s (first-min tie-break, matching jnp.argmin)
//   out[m,d] = (e[idx[m]][d] + x[m,d]) - x[m,d]    (exact straight-through)
// x2/e2 reduction order is argmin-irrelevant (grid-shift argument): x2 errors
// shift all of row m's scores by the same ulp(64)-grid amount, which commutes
// with the final rounding except at measure-zero midpoint events.
//
// [Round 3 resubmit: round-2 bench was an infra failure (container died), so
//  this is the identical kernel to get the precision-hypothesis A/B.]

#define DDIM 64
#define KC   512
#define BM   64          // queries per CTA
#define BN   128         // codes per chunk
#define NCHUNK (KC / BN) // 4
#define TPB  256
#define XS_STRIDE (BM + 4)   // 68 floats
#define ES_STRIDE (BN + 4)   // 132 floats

struct Smem {
    float XS[DDIM][XS_STRIDE];   // X tile, transposed: XS[d][m]
    float ES[DDIM][ES_STRIDE];   // E chunk, transposed: ES[d][n]
    float X2S[BM];               // ||x||^2 per row
    float E2C[BN];               // ||e||^2 for current chunk
    float REDV[BM][16];          // per-row argmin reduction (values)
    int   REDI[BM][16];          // per-row argmin reduction (indices)
    int   WIDX[BM];              // winning code per row
};

__global__ __launch_bounds__(TPB)
void vq_argmin_kernel(const float* __restrict__ X,
                      const float* __restrict__ E,
                      float* __restrict__ OUT)
{
    extern __shared__ char smem_raw[];
    Smem& s = *reinterpret_cast<Smem*>(smem_raw);

    const int tid = threadIdx.x;
    const int m0  = blockIdx.x * BM;

    // ---- Load X tile, transposed into smem (XS[d][m]) ----
    #pragma unroll 1
    for (int i = tid; i < BM * (DDIM / 4); i += TPB) {
        const int m = i % BM;
        const int c = i / BM;
        float4 v = *reinterpret_cast<const float4*>(X + (m0 + m) * DDIM + c * 4);
        s.XS[c * 4 + 0][m] = v.x;
        s.XS[c * 4 + 1][m] = v.y;
        s.XS[c * 4 + 2][m] = v.z;
        s.XS[c * 4 + 3][m] = v.w;
    }
    __syncthreads();

    // ---- ||x||^2 per row (mul then add; order argmin-irrelevant) ----
    if (tid < BM) {
        float acc2 = 0.f;
        #pragma unroll
        for (int d2 = 0; d2 < DDIM; d2++) {
            float v = s.XS[d2][tid];
            acc2 = __fadd_rn(acc2, __fmul_rn(v, v));
        }
        s.X2S[tid] = acc2;
    }

    const int ty = tid >> 4;        // 0..15
    const int tx = tid & 15;        // 0..15
    const int rm = ty * 4;          // 4 rows/thread
    const int cn = tx * 8;          // 8 cols/thread

    float bestv[4];
    int   besti[4];
    #pragma unroll
    for (int r = 0; r < 4; r++) { bestv[r] = 3.0e38f; besti[r] = 0; }

    for (int ch = 0; ch < NCHUNK; ch++) {
        __syncthreads();   // prev chunk's ES/E2C consumed (also orders XS/X2S on ch=0)

        // ---- Load E chunk, transposed into smem (ES[d][n]) ----
        #pragma unroll 1
        for (int i = tid; i < BN * (DDIM / 4); i += TPB) {
            const int n = i % BN;
            const int c = i / BN;
            float4 v = *reinterpret_cast<const float4*>(E + (ch * BN + n) * DDIM + c * 4);
            s.ES[c * 4 + 0][n] = v.x;
            s.ES[c * 4 + 1][n] = v.y;
            s.ES[c * 4 + 2][n] = v.z;
            s.ES[c * 4 + 3][n] = v.w;
        }
        __syncthreads();

        // ---- ||e||^2 for this chunk (mul then add) ----
        if (tid < BN) {
            float acc2 = 0.f;
            #pragma unroll
            for (int d2 = 0; d2 < DDIM; d2++) {
                float v = s.ES[d2][tid];
                acc2 = __fadd_rn(acc2, __fmul_rn(v, v));
            }
            s.E2C[tid] = acc2;
        }
        __syncthreads();

        // ---- Main FFMA loop: 4x8 register tile, sequential ascending over d ----
        float acc[4][8];
        #pragma unroll
        for (int r = 0; r < 4; r++)
            #pragma unroll
            for (int c = 0; c < 8; c++) acc[r][c] = 0.f;

        #pragma unroll 8
        for (int d = 0; d < DDIM; d++) {
            float4 a  = *reinterpret_cast<const float4*>(&s.XS[d][rm]);
            float4 b0 = *reinterpret_cast<const float4*>(&s.ES[d][cn]);
            float4 b1 = *reinterpret_cast<const float4*>(&s.ES[d][cn + 4]);
            const float av[4] = {a.x, a.y, a.z, a.w};
            const float bv[8] = {b0.x, b0.y, b0.z, b0.w, b1.x, b1.y, b1.z, b1.w};
            #pragma unroll
            for (int r = 0; r < 4; r++)
                #pragma unroll
                for (int c = 0; c < 8; c++)
                    acc[r][c] = __fmaf_rn(av[r], bv[c], acc[r][c]);
        }

        // ---- Exact reference scoring + running argmin (k ascending) ----
        float x2v[4];
        #pragma unroll
        for (int r = 0; r < 4; r++) x2v[r] = s.X2S[rm + r];

        #pragma unroll
        for (int c = 0; c < 8; c++) {
            const float e2 = s.E2C[cn + c];
            const int   k  = ch * BN + cn + c;
            #pragma unroll
            for (int r = 0; r < 4; r++) {
                // t2 = RN(x2 - 2*dot): 2*dot is exact, so FFMA == single rounding
                float t2 = __fmaf_rn(-2.0f, acc[r][c], x2v[r]);
                float sc = __fadd_rn(t2, e2);
                if (sc < bestv[r]) { bestv[r] = sc; besti[r] = k; }
            }
        }
    }

    // ---- Cross-thread argmin reduction (value, then lowest index on ties) ----
    #pragma unroll
    for (int r = 0; r < 4; r++) {
        s.REDV[rm + r][tx] = bestv[r];
        s.REDI[rm + r][tx] = besti[r];
    }
    __syncthreads();
    if (tid < BM) {
        float bv = s.REDV[tid][0];
        int   bi = s.REDI[tid][0];
        #pragma unroll
        for (int j = 1; j < 16; j++) {
            float v  = s.REDV[tid][j];
            int   ii = s.REDI[tid][j];
            if (v < bv || (v == bv && ii < bi)) { bv = v; bi = ii; }
        }
        s.WIDX[tid] = bi;
    }
    __syncthreads();

    // ---- Gather + straight-through output: out = (e + x) - x, coalesced ----
    #pragma unroll 1
    for (int i = tid; i < BM * (DDIM / 4); i += TPB) {
        const int m = i / (DDIM / 4);
        const int c = i % (DDIM / 4);
        const int k = s.WIDX[m];
        float4 e4 = *reinterpret_cast<const float4*>(E + k * DDIM + c * 4);
        float4 x4 = *reinterpret_cast<const float4*>(X + (m0 + m) * DDIM + c * 4);
        float4 o;
        o.x = __fsub_rn(__fadd_rn(e4.x, x4.x), x4.x);
        o.y = __fsub_rn(__fadd_rn(e4.y, x4.y), x4.y);
        o.z = __fsub_rn(__fadd_rn(e4.z, x4.z), x4.z);
        o.w = __fsub_rn(__fadd_rn(e4.w, x4.w), x4.w);
        *reinterpret_cast<float4*>(OUT + (m0 + m) * DDIM + c * 4) = o;
    }
}

extern "C" void kernel_launch(void* const* d_in, const int* in_sizes, int n_in,
                              void* d_out, int out_size)
{
    const float* a0 = (const float*)d_in[0];
    const float* a1 = (const float*)d_in[1];
    const float *X, *E;
    int M;
    if (n_in >= 2 && in_sizes[0] == KC * DDIM && in_sizes[1] != KC * DDIM) {
        E = a0; X = a1; M = in_sizes[1] / DDIM;
    } else {
        X = a0; E = a1; M = in_sizes[0] / DDIM;
    }
    float* OUT = (float*)d_out;

    const int shmem = (int)sizeof(Smem);
    cudaFuncSetAttribute(vq_argmin_kernel,
                         cudaFuncAttributeMaxDynamicSharedMemorySize, shmem);

    dim3 grid(M / BM);
    vq_argmin_kernel<<<grid, TPB, shmem>>>(X, E, OUT);
}

// round 4
// speedup vs baseline: 1.6525x; 1.6525x over previous
#include <cuda_runtime.h>

// VQ-VAE nearest-codebook quantization, fused. Scoring emulates the reference
// bitwise (validated rel_err==0 in round 3):
//   dot[m,k] = sequential ascending fp32 FMA chain over d
//   t2       = RN(x2[m] - 2*dot)   (FFMA(-2,dot,x2): 2*dot exact -> 1 rounding)
//   s        = RN(t2 + e2[k]);  argmin_k with first-min tie-break
//   out      = (e[idx] + x) - x
//
// Round 4: ncu showed L1/smem-crossbar bound (L1=73.5%, fma=26.1%).
//  -> 8x8 register tile (1B LDS per FMA instead of 1.5B)
//  -> split-offset col/row mapping (tx*4 and 64+tx*4): each 8-lane LDS phase
//     spans 128B at 16B stride => conflict-free smem reads
//  -> warp-shuffle argmin reduction (no smem round-trip)

#define DDIM 64
#define KC   512
#define BM   128         // queries per CTA
#define BN   128         // codes per chunk
#define NCHUNK (KC / BN) // 4
#define TPB  256
#define XS_STRIDE (BM + 4)   // 132 floats (16B-aligned rows: 528B)
#define ES_STRIDE (BN + 4)   // 132 floats

struct Smem {
    float XS[DDIM][XS_STRIDE];   // X tile, transposed: XS[d][m]
    float ES[DDIM][ES_STRIDE];   // E chunk, transposed: ES[d][n]
    float X2S[BM];               // ||x||^2 per row
    float E2C[BN];               // ||e||^2 for current chunk
    int   WIDX[BM];              // winning code per row
};

__global__ __launch_bounds__(TPB)
void vq_argmin_kernel(const float* __restrict__ X,
                      const float* __restrict__ E,
                      float* __restrict__ OUT)
{
    extern __shared__ char smem_raw[];
    Smem& s = *reinterpret_cast<Smem*>(smem_raw);

    const int tid = threadIdx.x;
    const int m0  = blockIdx.x * BM;

    // ---- Load X tile, transposed into smem (XS[d][m]) ----
    #pragma unroll 1
    for (int i = tid; i < BM * (DDIM / 4); i += TPB) {
        const int m = i % BM;              // consecutive threads -> consecutive m
        const int c = i / BM;
        float4 v = *reinterpret_cast<const float4*>(X + (m0 + m) * DDIM + c * 4);
        s.XS[c * 4 + 0][m] = v.x;
        s.XS[c * 4 + 1][m] = v.y;
        s.XS[c * 4 + 2][m] = v.z;
        s.XS[c * 4 + 3][m] = v.w;
    }
    __syncthreads();

    // ---- ||x||^2 per row (mul then add; order argmin-irrelevant) ----
    if (tid < BM) {
        float acc2 = 0.f;
        #pragma unroll
        for (int d2 = 0; d2 < DDIM; d2++) {
            float v = s.XS[d2][tid];
            acc2 = __fadd_rn(acc2, __fmul_rn(v, v));
        }
        s.X2S[tid] = acc2;
    }

    const int tx  = tid & 15;       // 0..15
    const int ty  = tid >> 4;       // 0..15
    const int tx4 = tx * 4;
    const int ty4 = ty * 4;
    // Thread's 8 rows: {ty4..ty4+3} U {64+ty4..64+ty4+3}
    // Thread's 8 cols: {tx4..tx4+3} U {64+tx4..64+tx4+3}

    float bestv[8];
    int   besti[8];
    #pragma unroll
    for (int r = 0; r < 8; r++) { bestv[r] = 3.0e38f; besti[r] = 0; }

    for (int ch = 0; ch < NCHUNK; ch++) {
        __syncthreads();   // prev chunk's ES/E2C consumed (also orders XS/X2S on ch=0)

        // ---- Load E chunk, transposed into smem (ES[d][n]) ----
        #pragma unroll 1
        for (int i = tid; i < BN * (DDIM / 4); i += TPB) {
            const int n = i % BN;
            const int c = i / BN;
            float4 v = *reinterpret_cast<const float4*>(E + (ch * BN + n) * DDIM + c * 4);
            s.ES[c * 4 + 0][n] = v.x;
            s.ES[c * 4 + 1][n] = v.y;
            s.ES[c * 4 + 2][n] = v.z;
            s.ES[c * 4 + 3][n] = v.w;
        }
        __syncthreads();

        // ---- ||e||^2 for this chunk (mul then add) ----
        if (tid < BN) {
            float acc2 = 0.f;
            #pragma unroll
            for (int d2 = 0; d2 < DDIM; d2++) {
                float v = s.ES[d2][tid];
                acc2 = __fadd_rn(acc2, __fmul_rn(v, v));
            }
            s.E2C[tid] = acc2;
        }
        __syncthreads();

        // ---- Main loop: 8x8 register tile, 4 conflict-free LDS.128 / 64 FFMA ----
        float acc[8][8];
        #pragma unroll
        for (int r = 0; r < 8; r++)
            #pragma unroll
            for (int c = 0; c < 8; c++) acc[r][c] = 0.f;

        #pragma unroll 2
        for (int d = 0; d < DDIM; d++) {
            float4 a0 = *reinterpret_cast<const float4*>(&s.XS[d][ty4]);
            float4 a1 = *reinterpret_cast<const float4*>(&s.XS[d][64 + ty4]);
            float4 b0 = *reinterpret_cast<const float4*>(&s.ES[d][tx4]);
            float4 b1 = *reinterpret_cast<const float4*>(&s.ES[d][64 + tx4]);
            const float av[8] = {a0.x, a0.y, a0.z, a0.w, a1.x, a1.y, a1.z, a1.w};
            const float bv[8] = {b0.x, b0.y, b0.z, b0.w, b1.x, b1.y, b1.z, b1.w};
            #pragma unroll
            for (int r = 0; r < 8; r++)
                #pragma unroll
                for (int c = 0; c < 8; c++)
                    acc[r][c] = __fmaf_rn(av[r], bv[c], acc[r][c]);
        }

        // ---- Exact reference scoring + running argmin ----
        #pragma unroll
        for (int r = 0; r < 8; r++) {
            const int gr  = (r < 4) ? (ty4 + r) : (64 + ty4 + (r - 4));
            const float x2 = s.X2S[gr];
            #pragma unroll
            for (int c = 0; c < 8; c++) {
                const int gc = (c < 4) ? (tx4 + c) : (64 + tx4 + (c - 4));
                const int k  = ch * BN + gc;
                float t2 = __fmaf_rn(-2.0f, acc[r][c], x2);
                float sc = __fadd_rn(t2, s.E2C[gc]);
                // k increases monotonically across chunks for fixed gc-slot? No:
                // within a row, each (ch,c) gives a distinct k; strict < keeps the
                // first (lowest-k) minimum only if we scan k ascending per slot.
                // Ties across different slots are resolved in the shuffle reduce.
                if (sc < bestv[r] || (sc == bestv[r] && k < besti[r])) {
                    bestv[r] = sc; besti[r] = k;
                }
            }
        }
    }

    // ---- 16-lane shuffle butterfly argmin (lanes share ty within a warp) ----
    #pragma unroll
    for (int off = 1; off < 16; off <<= 1) {
        #pragma unroll
        for (int r = 0; r < 8; r++) {
            float ov = __shfl_xor_sync(0xffffffffu, bestv[r], off);
            int   oi = __shfl_xor_sync(0xffffffffu, besti[r], off);
            if (ov < bestv[r] || (ov == bestv[r] && oi < besti[r])) {
                bestv[r] = ov; besti[r] = oi;
            }
        }
    }
    if (tx == 0) {
        #pragma unroll
        for (int r = 0; r < 8; r++) {
            const int gr = (r < 4) ? (ty4 + r) : (64 + ty4 + (r - 4));
            s.WIDX[gr] = besti[r];
        }
    }
    __syncthreads();

    // ---- Gather + straight-through output: out = (e + x) - x, coalesced ----
    #pragma unroll 1
    for (int i = tid; i < BM * (DDIM / 4); i += TPB) {
        const int m = i / (DDIM / 4);   // consecutive threads -> consecutive c
        const int c = i % (DDIM / 4);
        const int k = s.WIDX[m];
        float4 e4 = *reinterpret_cast<const float4*>(E + k * DDIM + c * 4);
        float4 x4 = *reinterpret_cast<const float4*>(X + (m0 + m) * DDIM + c * 4);
        float4 o;
        o.x = __fsub_rn(__fadd_rn(e4.x, x4.x), x4.x);
        o.y = __fsub_rn(__fadd_rn(e4.y, x4.y), x4.y);
        o.z = __fsub_rn(__fadd_rn(e4.z, x4.z), x4.z);
        o.w = __fsub_rn(__fadd_rn(e4.w, x4.w), x4.w);
        *reinterpret_cast<float4*>(OUT + (m0 + m) * DDIM + c * 4) = o;
    }
}

extern "C" void kernel_launch(void* const* d_in, const int* in_sizes, int n_in,
                              void* d_out, int out_size)
{
    const float* a0 = (const float*)d_in[0];
    const float* a1 = (const float*)d_in[1];
    const float *X, *E;
    int M;
    if (n_in >= 2 && in_sizes[0] == KC * DDIM && in_sizes[1] != KC * DDIM) {
        E = a0; X = a1; M = in_sizes[1] / DDIM;
    } else {
        X = a0; E = a1; M = in_sizes[0] / DDIM;
    }
    float* OUT = (float*)d_out;

    const int shmem = (int)sizeof(Smem);   // ~68 KB
    cudaFuncSetAttribute(vq_argmin_kernel,
                         cudaFuncAttributeMaxDynamicSharedMemorySize, shmem);

    dim3 grid(M / BM);   // 65536/128 = 512 CTAs
    vq_argmin_kernel<<<grid, TPB, shmem>>>(X, E, OUT);
}